// round 8
// baseline (speedup 1.0000x reference)
#include <cuda_runtime.h>

#define NPOS   80
#define VOCABX 256
#define HID    128
#define HID4   (HID / 4)        // 32 float4 per row
#define RPW    4                // rows per warp
#define NWARPS 8
#define TILE   (RPW * NWARPS)   // 32 rows per block

// Flag: 1 if message buffer is int64, 0 if int32. Set by detect_kernel.
__device__ int g_msg_is64;

__global__ void detect_dtype_kernel(const unsigned int* __restrict__ w, int nwords) {
    // If the message tensor is int64 (values < 256), every odd 32-bit word
    // (high half of each little-endian int64) is zero. If it is int32, odd
    // words are uniform random bytes in [0,256): P(64 consecutive zeros) ~ 0.
    int is64 = 1;
    int lim = nwords < 129 ? nwords : 129;
    for (int i = 1; i < lim; i += 2) {
        if (w[i] != 0u) { is64 = 0; break; }
    }
    g_msg_is64 = is64;
}

__device__ __forceinline__ float elu1(float x) {
    return x > 0.0f ? x : expm1f(x);
}

__device__ __forceinline__ float4 elu4(float4 v) {
    v.x = elu1(v.x); v.y = elu1(v.y); v.z = elu1(v.z); v.w = elu1(v.w);
    return v;
}

__device__ __forceinline__ void acc4(float4& a, const float4 v) {
    a.x += v.x; a.y += v.y; a.z += v.z; a.w += v.w;
}

__device__ __forceinline__ void fma4(float4& c, const float h, const float4 w) {
    c.x = fmaf(h, w.x, c.x);
    c.y = fmaf(h, w.y, c.y);
    c.z = fmaf(h, w.z, c.z);
    c.w = fmaf(h, w.w, c.w);
}

__global__ void __launch_bounds__(256)
topline_encoder_kernel(
    const void*  __restrict__ msg_raw,   // int64 or int32, per g_msg_is64
    const float4* __restrict__ W1,       // [20480][32] float4 view of [20480,128]
    const float*  __restrict__ b1,       // [128]
    const float4* __restrict__ W2,       // [128][32]  float4 view of [128,128]
    const float*  __restrict__ b2,       // [128]
    float4*       __restrict__ out,      // [B][32]
    int B)
{
    __shared__ int   offs[TILE][NPOS];   // W1 float4-row base offsets (rowIdx*32)
    __shared__ float hsm[TILE][HID];     // post-ELU hidden activations

    const int base = blockIdx.x * TILE;
    const int tid  = threadIdx.x;

    // ---- stage gather offsets for the block's 32 rows ----
    const int is64 = g_msg_is64;
    const long long*  msg64 = (const long long*)msg_raw;
    const int*        msg32 = (const int*)msg_raw;

    for (int i = tid; i < TILE * NPOS; i += 256) {
        int r = i / NPOS;
        int p = i - r * NPOS;
        int gr = base + r;
        int byte = 0;
        if (gr < B) {
            long long li = (long long)gr * NPOS + p;
            byte = is64 ? (int)msg64[li] : msg32[li];
        }
        offs[r][p] = (p * VOCABX + byte) * HID4;
    }
    __syncthreads();

    const int warp = tid >> 5;
    const int lane = tid & 31;
    const int r0   = warp * RPW;

    // ---- phase 1: gather-accumulate 4 rows (L2-only loads via __ldcg) ----
    float4 a0 = make_float4(0.f, 0.f, 0.f, 0.f);
    float4 a1 = a0, a2 = a0, a3 = a0;

    #pragma unroll 4
    for (int p = 0; p < NPOS; p++) {
        const int o0 = offs[r0 + 0][p];
        const int o1 = offs[r0 + 1][p];
        const int o2 = offs[r0 + 2][p];
        const int o3 = offs[r0 + 3][p];
        float4 v0 = __ldcg(&W1[o0 + lane]);
        float4 v1 = __ldcg(&W1[o1 + lane]);
        float4 v2 = __ldcg(&W1[o2 + lane]);
        float4 v3 = __ldcg(&W1[o3 + lane]);
        acc4(a0, v0);
        acc4(a1, v1);
        acc4(a2, v2);
        acc4(a3, v3);
    }

    // ---- bias + ELU -> shared ----
    const float4 bb1 = reinterpret_cast<const float4*>(b1)[lane];
    acc4(a0, bb1); acc4(a1, bb1); acc4(a2, bb1); acc4(a3, bb1);
    a0 = elu4(a0); a1 = elu4(a1); a2 = elu4(a2); a3 = elu4(a3);

    reinterpret_cast<float4*>(&hsm[r0 + 0][0])[lane] = a0;
    reinterpret_cast<float4*>(&hsm[r0 + 1][0])[lane] = a1;
    reinterpret_cast<float4*>(&hsm[r0 + 2][0])[lane] = a2;
    reinterpret_cast<float4*>(&hsm[r0 + 3][0])[lane] = a3;
    __syncwarp();

    // ---- phase 2: 4-row register-tiled GEMM h @ W2 + b2, ELU ----
    const float4 bb2 = reinterpret_cast<const float4*>(b2)[lane];
    float4 c0 = bb2, c1 = bb2, c2 = bb2, c3 = bb2;

    #pragma unroll 8
    for (int k = 0; k < HID; k++) {
        const float4 w = __ldg(&W2[k * HID4 + lane]);
        const float h0 = hsm[r0 + 0][k];
        const float h1 = hsm[r0 + 1][k];
        const float h2 = hsm[r0 + 2][k];
        const float h3 = hsm[r0 + 3][k];
        fma4(c0, h0, w);
        fma4(c1, h1, w);
        fma4(c2, h2, w);
        fma4(c3, h3, w);
    }

    c0 = elu4(c0); c1 = elu4(c1); c2 = elu4(c2); c3 = elu4(c3);

    if (base + r0 + 0 < B) out[(long long)(base + r0 + 0) * HID4 + lane] = c0;
    if (base + r0 + 1 < B) out[(long long)(base + r0 + 1) * HID4 + lane] = c1;
    if (base + r0 + 2 < B) out[(long long)(base + r0 + 2) * HID4 + lane] = c2;
    if (base + r0 + 3 < B) out[(long long)(base + r0 + 3) * HID4 + lane] = c3;
}

extern "C" void kernel_launch(void* const* d_in, const int* in_sizes, int n_in,
                              void* d_out, int out_size)
{
    const void*  msg = d_in[0];
    const float* W1  = (const float*)d_in[1];
    const float* b1  = (const float*)d_in[2];
    const float* W2  = (const float*)d_in[3];
    const float* b2  = (const float*)d_in[4];

    const int B = in_sizes[0] / NPOS;

    // dtype sniff (int64 vs silently-downgraded int32) — deterministic, capturable
    detect_dtype_kernel<<<1, 1>>>((const unsigned int*)msg, in_sizes[0]);

    dim3 grid((B + TILE - 1) / TILE);
    topline_encoder_kernel<<<grid, 256>>>(
        msg,
        (const float4*)W1, b1,
        (const float4*)W2, b2,
        (float4*)d_out, B);
}